// round 4
// baseline (speedup 1.0000x reference)
#include <cuda_runtime.h>
#include <math.h>

// ---------------- problem constants ----------------
#define NN   5000          // nodes
#define EE   80000         // edges
#define BB   8             // batch
#define IND  30            // input feature dim
#define HH   4             // heads
#define DD   64            // dim per head
#define HDIM 256           // HH*DD
#define OUTD 3
#define TT   5             // output_length (fixed for this problem)
#define ROWS (BB*NN)       // 40000

// ---------------- device scratch ----------------
__device__ float g_xx[ROWS*IND];        // rolling input window
__device__ float g_bufA[ROWS*HDIM];     // GEMM output h = xW
__device__ float g_bufB[ROWS*HDIM];     // aggregation output
__device__ float g_bufC[ROWS*HDIM];     // normalized+activated (next layer input)
__device__ float g_el[ROWS*HH];
__device__ float g_er[ROWS*HH];
__device__ int   g_deg[NN];
__device__ int   g_rowptr[NN+1];
__device__ int   g_cursor[NN];
__device__ int   g_csrsrc[EE];
__device__ float g_bnsum[HDIM];
__device__ float g_bnsq[HDIM];
__device__ float g_scale[HDIM];
__device__ float g_shift[HDIM];

// ---------------- graph preprocessing ----------------
__global__ void zeroi_k(int* p, int n) {
    int i = blockIdx.x*blockDim.x + threadIdx.x;
    if (i < n) p[i] = 0;
}

__global__ void hist_k(const int* __restrict__ dst) {
    int e = blockIdx.x*blockDim.x + threadIdx.x;
    if (e < EE) atomicAdd(&g_deg[dst[e]], 1);
}

// single-block Hillis-Steele scan over N=5000 (5 chunks of 1024)
__global__ void scan_k() {
    __shared__ int sm[1024];
    int t = threadIdx.x;
    int run = 0;
    for (int base = 0; base < NN; base += 1024) {
        int i = base + t;
        int v = (i < NN) ? g_deg[i] : 0;
        __syncthreads();           // protect sm reuse from previous chunk
        sm[t] = v;
        __syncthreads();
        for (int off = 1; off < 1024; off <<= 1) {
            int a = (t >= off) ? sm[t-off] : 0;
            __syncthreads();
            sm[t] += a;
            __syncthreads();
        }
        if (i < NN) g_rowptr[i+1] = run + sm[t];
        run += sm[1023];
    }
    if (t == 0) g_rowptr[0] = 0;
}

__global__ void csr_k(const int* __restrict__ src, const int* __restrict__ dst) {
    int e = blockIdx.x*blockDim.x + threadIdx.x;
    if (e < EE) {
        int d = dst[e];
        int pos = atomicAdd(&g_cursor[d], 1);
        g_csrsrc[g_rowptr[d] + pos] = src[e];
    }
}

// ---------------- SGEMM: C[M,Nc] = A[M,K] * B[K,Nc] ----------------
// classic 128x128x8, 8x8 per thread, 256 threads
__global__ __launch_bounds__(256) void sgemm_k(
    const float* __restrict__ A, const float* __restrict__ Bm,
    float* __restrict__ C, int M, int Nc, int K)
{
    const int BM = 128, BN = 128, BK = 8;
    __shared__ float As[BK][BM];
    __shared__ float Bs[BK][BN];
    int tid = threadIdx.x;
    int tx = tid & 15, ty = tid >> 4;
    int bx = blockIdx.x, by = blockIdx.y;

    int arow = tid >> 1, acol = (tid & 1) << 2;   // A: 128 rows x 8 cols
    int brow = tid >> 5, bcol = (tid & 31) << 2;  // B: 8 rows x 128 cols

    const float* Ap = A + (long)(by * BM) * K;
    const float* Bp = Bm + bx * BN;
    bool aok = (by * BM + arow) < M;

    float acc[8][8];
#pragma unroll
    for (int i = 0; i < 8; i++)
#pragma unroll
        for (int j = 0; j < 8; j++) acc[i][j] = 0.f;

    for (int kt = 0; kt < K; kt += BK) {
#pragma unroll
        for (int i = 0; i < 4; i++) {
            int k = kt + acol + i;
            As[acol + i][arow] = (aok && k < K) ? Ap[(long)arow * K + k] : 0.f;
        }
        int kb = kt + brow;
#pragma unroll
        for (int i = 0; i < 4; i++) {
            Bs[brow][bcol + i] = (kb < K) ? Bp[(long)kb * Nc + bcol + i] : 0.f;
        }
        __syncthreads();
#pragma unroll
        for (int kk = 0; kk < BK; kk++) {
            float ra[8], rb[8];
#pragma unroll
            for (int i = 0; i < 8; i++) ra[i] = As[kk][ty * 8 + i];
#pragma unroll
            for (int j = 0; j < 8; j++) rb[j] = Bs[kk][tx * 8 + j];
#pragma unroll
            for (int i = 0; i < 8; i++)
#pragma unroll
                for (int j = 0; j < 8; j++) acc[i][j] += ra[i] * rb[j];
        }
        __syncthreads();
    }
#pragma unroll
    for (int i = 0; i < 8; i++) {
        int row = by * BM + ty * 8 + i;
        if (row < M) {
            float* Cp = C + (long)row * Nc + bx * BN + tx * 8;
#pragma unroll
            for (int j = 0; j < 8; j++) Cp[j] = acc[i][j];
        }
    }
}

// ---------------- attention logits el/er: one warp per (b,n) ----------------
__global__ void elr_k(const float* __restrict__ h,
                      const float* __restrict__ al, const float* __restrict__ ar)
{
    int g = blockIdx.x*blockDim.x + threadIdx.x;
    int w = g >> 5;
    if (w >= ROWS) return;
    int lane = g & 31;
    const float* hp = h + (long)w * HDIM + lane * 8;
    float sl = 0.f, sr = 0.f;
#pragma unroll
    for (int i = 0; i < 8; i++) {
        float v = hp[i];
        int c = lane * 8 + i;
        sl += v * al[c];
        sr += v * ar[c];
    }
    // reduce within each 8-lane group (one head per 8 lanes)
#pragma unroll
    for (int off = 1; off < 8; off <<= 1) {
        sl += __shfl_xor_sync(0xffffffffu, sl, off);
        sr += __shfl_xor_sync(0xffffffffu, sr, off);
    }
    if ((lane & 7) == 0) {
        g_el[w * HH + (lane >> 3)] = sl;
        g_er[w * HH + (lane >> 3)] = sr;
    }
}

// ---------------- edge softmax + aggregation: one block per (b,n) ----------------
__global__ __launch_bounds__(256) void attn_k(const float* __restrict__ h,
                                              float* __restrict__ out)
{
    int bn = blockIdx.x;
    int n = bn % NN;
    int b = bn / NN;
    int tid = threadIdx.x;

    __shared__ float s_er[HH], s_m[HH], s_inv[HH];
    __shared__ float s_red[32];
    __shared__ int   s_src[128];
    __shared__ float s_alpha[128 * HH];

    int start = g_rowptr[n];
    int deg   = g_rowptr[n+1] - start;

    if (tid < HH) s_er[tid] = g_er[bn * HH + tid];
    __syncthreads();

    if (deg == 0) { out[(long)bn * HDIM + tid] = 0.f; return; }

    int hh = tid & 3;
    float erh = s_er[hh];

    // pass 1: segment max
    float lmax = -1e30f;
    for (int e = tid >> 2; e < deg; e += 64) {
        int s = g_csrsrc[start + e];
        float z = g_el[(b * NN + s) * HH + hh] + erh;
        z = z > 0.f ? z : 0.2f * z;
        lmax = fmaxf(lmax, z);
    }
#pragma unroll
    for (int off = 4; off <= 16; off <<= 1)
        lmax = fmaxf(lmax, __shfl_xor_sync(0xffffffffu, lmax, off));
    int warp = tid >> 5, lane = tid & 31;
    if (lane < 4) s_red[warp * 4 + lane] = lmax;
    __syncthreads();
    if (tid < 4) {
        float m = s_red[tid];
#pragma unroll
        for (int w2 = 1; w2 < 8; w2++) m = fmaxf(m, s_red[w2 * 4 + tid]);
        s_m[tid] = m;
    }
    __syncthreads();

    // pass 2: sum of exp
    float mh = s_m[hh];
    float lsum = 0.f;
    for (int e = tid >> 2; e < deg; e += 64) {
        int s = g_csrsrc[start + e];
        float z = g_el[(b * NN + s) * HH + hh] + erh;
        z = z > 0.f ? z : 0.2f * z;
        lsum += expf(z - mh);
    }
#pragma unroll
    for (int off = 4; off <= 16; off <<= 1)
        lsum += __shfl_xor_sync(0xffffffffu, lsum, off);
    if (lane < 4) s_red[warp * 4 + lane] = lsum;
    __syncthreads();
    if (tid < 4) {
        float sm = 0.f;
#pragma unroll
        for (int w2 = 0; w2 < 8; w2++) sm += s_red[w2 * 4 + tid];
        s_inv[tid] = 1.f / sm;
    }
    __syncthreads();

    // pass 3: alpha in smem, gather-accumulate; thread owns channel tid
    int ch = tid >> 6;
    float acc = 0.f;
    for (int cb = 0; cb < deg; cb += 128) {
        int cnt = min(128, deg - cb);
        if (tid < cnt) s_src[tid] = g_csrsrc[start + cb + tid];
        for (int idx = tid; idx < cnt * HH; idx += 256) {
            int e = idx >> 2, h2 = idx & 3;
            int s = g_csrsrc[start + cb + e];
            float z = g_el[(b * NN + s) * HH + h2] + s_er[h2];
            z = z > 0.f ? z : 0.2f * z;
            s_alpha[idx] = expf(z - s_m[h2]) * s_inv[h2];
        }
        __syncthreads();
        for (int j = 0; j < cnt; j++) {
            acc += s_alpha[j * HH + ch] * h[(long)(b * NN + s_src[j]) * HDIM + tid];
        }
        __syncthreads();
    }
    out[(long)bn * HDIM + tid] = acc;
}

// ---------------- BatchNorm (training stats over B*N) ----------------
__global__ void bnzero_k() {
    g_bnsum[threadIdx.x] = 0.f;
    g_bnsq[threadIdx.x]  = 0.f;
}

__global__ void bnred_k(const float* __restrict__ x) {
    int t = threadIdx.x;   // channel
    float s = 0.f, q = 0.f;
    for (int r = blockIdx.x; r < ROWS; r += gridDim.x) {
        float v = x[(long)r * HDIM + t];
        s += v; q += v * v;
    }
    atomicAdd(&g_bnsum[t], s);
    atomicAdd(&g_bnsq[t], q);
}

__global__ void bnfin_k(const float* __restrict__ gamma, const float* __restrict__ beta) {
    int t = threadIdx.x;
    const float inv = 1.f / (float)ROWS;
    float mu  = g_bnsum[t] * inv;
    float var = g_bnsq[t] * inv - mu * mu;
    float r = rsqrtf(var + 1e-5f);
    float sc = r * gamma[t];
    g_scale[t] = sc;
    g_shift[t] = beta[t] - mu * sc;
}

__global__ void normact_k(const float* __restrict__ x, float* __restrict__ y) {
    long i = (long)blockIdx.x * blockDim.x + threadIdx.x;
    if (i >= (long)ROWS * HDIM) return;
    int c = (int)(i & (HDIM - 1));
    float v = x[i] * g_scale[c] + g_shift[c];
    y[i] = v > 0.f ? v : 0.01f * v;
}

// ---------------- output projection + xx window shift ----------------
__global__ void outproj_k(const float* __restrict__ h, const float* __restrict__ Wout,
                          const float* __restrict__ bout, float* __restrict__ dout, int step)
{
    int g = blockIdx.x*blockDim.x + threadIdx.x;
    int w = g >> 5;
    if (w >= ROWS) return;
    int lane = g & 31;
    const float* hp = h + (long)w * HDIM + lane * 8;
    float p0 = 0.f, p1 = 0.f, p2 = 0.f;
#pragma unroll
    for (int i = 0; i < 8; i++) {
        float v = hp[i];
        int c = lane * 8 + i;
        p0 += v * Wout[c * 3 + 0];
        p1 += v * Wout[c * 3 + 1];
        p2 += v * Wout[c * 3 + 2];
    }
#pragma unroll
    for (int off = 1; off < 32; off <<= 1) {
        p0 += __shfl_xor_sync(0xffffffffu, p0, off);
        p1 += __shfl_xor_sync(0xffffffffu, p1, off);
        p2 += __shfl_xor_sync(0xffffffffu, p2, off);
    }
    if (lane == 0) {
        p0 += bout[0]; p1 += bout[1]; p2 += bout[2];
        // shift sliding window xx[..., :27] = xx[..., 3:], append new out
        float* xr = g_xx + (long)w * IND;
        float tmp[IND - 3];
#pragma unroll
        for (int i = 0; i < IND - 3; i++) tmp[i] = xr[i + 3];
#pragma unroll
        for (int i = 0; i < IND - 3; i++) xr[i] = tmp[i];
        xr[IND - 3] = p0; xr[IND - 2] = p1; xr[IND - 1] = p2;
        // d_out layout [B, N, T, OUT]
        float* op = dout + ((long)w * TT + step) * OUTD;
        op[0] = p0; op[1] = p1; op[2] = p2;
    }
}

// ---------------- launcher ----------------
extern "C" void kernel_launch(void* const* d_in, const int* in_sizes, int n_in,
                              void* d_out, int out_size)
{
    const float* xx_in = (const float*)d_in[0];
    const int*   src   = (const int*)d_in[1];
    const int*   dst   = (const int*)d_in[2];
    const float *W[4], *al[4], *ar[4], *gm[4], *bt[4];
    for (int l = 0; l < 4; l++) {
        W[l]  = (const float*)d_in[3 + l*5];
        al[l] = (const float*)d_in[4 + l*5];
        ar[l] = (const float*)d_in[5 + l*5];
        gm[l] = (const float*)d_in[6 + l*5];
        bt[l] = (const float*)d_in[7 + l*5];
    }
    const float* Wout = (const float*)d_in[23];
    const float* bout = (const float*)d_in[24];
    float* dout = (float*)d_out;

    float *xxp, *bufA, *bufB, *bufC;
    int *degp, *curp;
    cudaGetSymbolAddress((void**)&xxp,  g_xx);
    cudaGetSymbolAddress((void**)&bufA, g_bufA);
    cudaGetSymbolAddress((void**)&bufB, g_bufB);
    cudaGetSymbolAddress((void**)&bufC, g_bufC);
    cudaGetSymbolAddress((void**)&degp, g_deg);
    cudaGetSymbolAddress((void**)&curp, g_cursor);

    // build CSR from dst (graph is fixed, rebuilt each call for determinism rules)
    zeroi_k<<<(NN + 255) / 256, 256>>>(degp, NN);
    zeroi_k<<<(NN + 255) / 256, 256>>>(curp, NN);
    hist_k<<<(EE + 255) / 256, 256>>>(dst);
    scan_k<<<1, 1024>>>();
    csr_k<<<(EE + 255) / 256, 256>>>(src, dst);

    cudaMemcpyAsync(xxp, xx_in, sizeof(float) * (size_t)ROWS * IND,
                    cudaMemcpyDeviceToDevice);

    for (int step = 0; step < TT; step++) {
        const float* in = xxp;
        int K = IND;
        for (int l = 0; l < 4; l++) {
            dim3 g(HDIM / 128, (ROWS + 127) / 128);
            sgemm_k<<<g, 256>>>(in, W[l], bufA, ROWS, HDIM, K);
            elr_k<<<(ROWS * 32 + 255) / 256, 256>>>(bufA, al[l], ar[l]);
            attn_k<<<ROWS, 256>>>(bufA, bufB);
            bnzero_k<<<1, 256>>>();
            bnred_k<<<256, 256>>>(bufB);
            bnfin_k<<<1, 256>>>(gm[l], bt[l]);
            normact_k<<<(ROWS * HDIM + 255) / 256, 256>>>(bufB, bufC);
            in = bufC;
            K = HDIM;
        }
        outproj_k<<<(ROWS * 32 + 255) / 256, 256>>>(bufC, Wout, bout, dout, step);
    }
}

// round 5
// speedup vs baseline: 2.0529x; 2.0529x over previous
#include <cuda_runtime.h>
#include <mma.h>
#include <math.h>

using namespace nvcuda;

// ---------------- problem constants ----------------
#define NN   5000          // nodes
#define EE   80000         // edges
#define BB   8             // batch
#define IND  30            // input feature dim
#define INDP 32            // padded K for layer-0 GEMM
#define HH   4             // heads
#define DD   64            // dim per head
#define HDIM 256           // HH*DD
#define OUTD 3
#define TT   5             // output_length
#define ROWS (BB*NN)       // 40000
#define ROWSP 40064        // padded to multiple of 128

// ---------------- device scratch ----------------
__device__ float g_xx[ROWSP*INDP];      // rolling input window, padded [ROWSP][32]
__device__ float g_W0p[INDP*HDIM];      // zero-padded W0
__device__ float g_bufA[ROWSP*HDIM];    // GEMM output h = xW
__device__ float g_bufB[ROWSP*HDIM];    // aggregation output
__device__ float g_bufC[ROWSP*HDIM];    // normalized+activated (next layer input)
__device__ float g_el[ROWS*HH];
__device__ float g_er[ROWS*HH];
__device__ int   g_deg[NN];
__device__ int   g_rowptr[NN+1];
__device__ int   g_cursor[NN];
__device__ int   g_csrsrc[EE];
__device__ float g_bnpart[2*256*HDIM];  // per-block partial sums / sq-sums
__device__ float g_scale[HDIM];
__device__ float g_shift[HDIM];

// ---------------- graph preprocessing ----------------
__global__ void zeroi_k(int* p, int n) {
    int i = blockIdx.x*blockDim.x + threadIdx.x;
    if (i < n) p[i] = 0;
}

__global__ void hist_k(const int* __restrict__ dst) {
    int e = blockIdx.x*blockDim.x + threadIdx.x;
    if (e < EE) atomicAdd(&g_deg[dst[e]], 1);
}

// single-block Hillis-Steele scan over N=5000 (5 chunks of 1024)
__global__ void scan_k() {
    __shared__ int sm[1024];
    int t = threadIdx.x;
    int run = 0;
    for (int base = 0; base < NN; base += 1024) {
        int i = base + t;
        int v = (i < NN) ? g_deg[i] : 0;
        __syncthreads();
        sm[t] = v;
        __syncthreads();
        for (int off = 1; off < 1024; off <<= 1) {
            int a = (t >= off) ? sm[t-off] : 0;
            __syncthreads();
            sm[t] += a;
            __syncthreads();
        }
        if (i < NN) g_rowptr[i+1] = run + sm[t];
        run += sm[1023];
    }
    if (t == 0) g_rowptr[0] = 0;
}

__global__ void csr_k(const int* __restrict__ src, const int* __restrict__ dst) {
    int e = blockIdx.x*blockDim.x + threadIdx.x;
    if (e < EE) {
        int d = dst[e];
        int pos = atomicAdd(&g_cursor[d], 1);
        g_csrsrc[g_rowptr[d] + pos] = src[e];
    }
}

// ---------------- init: pack xx into padded layout, pad W0 ----------------
__global__ void initxx_k(const float* __restrict__ xx) {
    int i = blockIdx.x*blockDim.x + threadIdx.x;
    if (i >= ROWSP*INDP) return;
    int r = i >> 5, c = i & 31;
    float v = 0.f;
    if (r < ROWS && c < IND) v = xx[r*IND + c];
    g_xx[i] = v;
}

__global__ void padw0_k(const float* __restrict__ W0) {
    int i = blockIdx.x*blockDim.x + threadIdx.x;
    if (i >= INDP*HDIM) return;
    int k = i / HDIM;
    g_W0p[i] = (k < IND) ? W0[i] : 0.f;
}

// ---------------- tf32-split tensor-core GEMM ----------------
// C[M=ROWSP, N=256] = A[M,K] * B[K,256], K in {32,256}, multiple of 16.
// Block tile 128x128, 8 warps (4M x 2N), warp tile 32x64.
// 2-term tf32 split (hi*hi + hi*lo + lo*hi) keeps ~fp32 accuracy.
#define LDA 20
#define LDB 136

__global__ __launch_bounds__(256, 2) void gemm_tf32_k(
    const float* __restrict__ A, const float* __restrict__ B,
    float* __restrict__ C, int K)
{
    __shared__ float As[128*LDA];
    __shared__ float Bs[16*LDB];

    int tid = threadIdx.x;
    int bx = blockIdx.x, by = blockIdx.y;
    int wid = tid >> 5;
    int wm = wid & 3;        // 0..3 -> rows wm*32
    int wn = wid >> 2;       // 0..1 -> cols wn*64

    wmma::fragment<wmma::accumulator,16,16,8,float> acc[2][4];
#pragma unroll
    for (int mi = 0; mi < 2; mi++)
#pragma unroll
        for (int ni = 0; ni < 4; ni++)
            wmma::fill_fragment(acc[mi][ni], 0.0f);

    const float* Ab = A + (long)(by * 128) * K;
    const float* Bb = B + bx * 128;

    int arow = tid >> 1, acol = (tid & 1) * 8;   // 128 rows x 16 cols
    int brow = tid >> 4, bcol = (tid & 15) * 8;  // 16 rows x 128 cols

    for (int kt = 0; kt < K; kt += 16) {
        *(float4*)&As[arow*LDA + acol]     = *(const float4*)&Ab[(long)arow*K + kt + acol];
        *(float4*)&As[arow*LDA + acol + 4] = *(const float4*)&Ab[(long)arow*K + kt + acol + 4];
        *(float4*)&Bs[brow*LDB + bcol]     = *(const float4*)&Bb[(long)(kt + brow)*HDIM + bcol];
        *(float4*)&Bs[brow*LDB + bcol + 4] = *(const float4*)&Bb[(long)(kt + brow)*HDIM + bcol + 4];
        __syncthreads();

#pragma unroll
        for (int k8 = 0; k8 < 16; k8 += 8) {
            wmma::fragment<wmma::matrix_a,16,16,8,wmma::precision::tf32,wmma::row_major> a_hi[2], a_lo[2];
#pragma unroll
            for (int mi = 0; mi < 2; mi++) {
                wmma::load_matrix_sync(a_hi[mi], &As[(wm*32 + mi*16)*LDA + k8], LDA);
#pragma unroll
                for (int t = 0; t < a_hi[mi].num_elements; t++) {
                    float x = a_hi[mi].x[t];
                    float hv = wmma::__float_to_tf32(x);
                    a_hi[mi].x[t] = hv;
                    a_lo[mi].x[t] = wmma::__float_to_tf32(x - hv);
                }
            }
#pragma unroll
            for (int ni = 0; ni < 4; ni++) {
                wmma::fragment<wmma::matrix_b,16,16,8,wmma::precision::tf32,wmma::row_major> b_hi, b_lo;
                wmma::load_matrix_sync(b_hi, &Bs[k8*LDB + wn*64 + ni*16], LDB);
#pragma unroll
                for (int t = 0; t < b_hi.num_elements; t++) {
                    float x = b_hi.x[t];
                    float hv = wmma::__float_to_tf32(x);
                    b_hi.x[t] = hv;
                    b_lo.x[t] = wmma::__float_to_tf32(x - hv);
                }
#pragma unroll
                for (int mi = 0; mi < 2; mi++) {
                    wmma::mma_sync(acc[mi][ni], a_hi[mi], b_hi, acc[mi][ni]);
                    wmma::mma_sync(acc[mi][ni], a_hi[mi], b_lo, acc[mi][ni]);
                    wmma::mma_sync(acc[mi][ni], a_lo[mi], b_hi, acc[mi][ni]);
                }
            }
        }
        __syncthreads();
    }

#pragma unroll
    for (int mi = 0; mi < 2; mi++)
#pragma unroll
        for (int ni = 0; ni < 4; ni++) {
            long row = by*128 + wm*32 + mi*16;
            int  col = bx*128 + wn*64 + ni*16;
            wmma::store_matrix_sync(&C[row*HDIM + col], acc[mi][ni], HDIM, wmma::mem_row_major);
        }
}

// ---------------- attention logits el/er: one warp per (b,n) ----------------
__global__ void elr_k(const float* __restrict__ h,
                      const float* __restrict__ al, const float* __restrict__ ar)
{
    int g = blockIdx.x*blockDim.x + threadIdx.x;
    int w = g >> 5;
    if (w >= ROWS) return;
    int lane = g & 31;
    const float4* hp  = (const float4*)(h + (long)w*HDIM) + lane*2;
    const float4* alp = (const float4*)al + lane*2;
    const float4* arp = (const float4*)ar + lane*2;
    float sl = 0.f, sr = 0.f;
#pragma unroll
    for (int i = 0; i < 2; i++) {
        float4 v = hp[i], a = alp[i], r = arp[i];
        sl += v.x*a.x + v.y*a.y + v.z*a.z + v.w*a.w;
        sr += v.x*r.x + v.y*r.y + v.z*r.z + v.w*r.w;
    }
#pragma unroll
    for (int off = 1; off < 8; off <<= 1) {
        sl += __shfl_xor_sync(0xffffffffu, sl, off);
        sr += __shfl_xor_sync(0xffffffffu, sr, off);
    }
    if ((lane & 7) == 0) {
        g_el[w * HH + (lane >> 3)] = sl;
        g_er[w * HH + (lane >> 3)] = sr;
    }
}

// ---------------- edge softmax + aggregation: one block per (b,n) ----------------
__global__ __launch_bounds__(256) void attn_k(const float* __restrict__ h,
                                              float* __restrict__ out)
{
    int bn = blockIdx.x;
    int n = bn % NN;
    int b = bn / NN;
    int tid = threadIdx.x;

    __shared__ float s_er[HH], s_m[HH], s_inv[HH];
    __shared__ float s_red[32];
    __shared__ int   s_src[128];
    __shared__ float s_alpha[128 * HH];
    __shared__ float4 s_acc[4][64];

    int start = g_rowptr[n];
    int deg   = g_rowptr[n+1] - start;

    if (tid < HH) s_er[tid] = g_er[bn * HH + tid];
    __syncthreads();

    if (deg == 0) { out[(long)bn * HDIM + tid] = 0.f; return; }

    int hh = tid & 3;
    float erh = s_er[hh];

    // pass 1: segment max
    float lmax = -1e30f;
    for (int e = tid >> 2; e < deg; e += 64) {
        int s = g_csrsrc[start + e];
        float z = g_el[(b * NN + s) * HH + hh] + erh;
        z = z > 0.f ? z : 0.2f * z;
        lmax = fmaxf(lmax, z);
    }
#pragma unroll
    for (int off = 4; off <= 16; off <<= 1)
        lmax = fmaxf(lmax, __shfl_xor_sync(0xffffffffu, lmax, off));
    int warp = tid >> 5, lane = tid & 31;
    if (lane < 4) s_red[warp * 4 + lane] = lmax;
    __syncthreads();
    if (tid < 4) {
        float m = s_red[tid];
#pragma unroll
        for (int w2 = 1; w2 < 8; w2++) m = fmaxf(m, s_red[w2 * 4 + tid]);
        s_m[tid] = m;
    }
    __syncthreads();

    // pass 2: sum of exp
    float mh = s_m[hh];
    float lsum = 0.f;
    for (int e = tid >> 2; e < deg; e += 64) {
        int s = g_csrsrc[start + e];
        float z = g_el[(b * NN + s) * HH + hh] + erh;
        z = z > 0.f ? z : 0.2f * z;
        lsum += expf(z - mh);
    }
#pragma unroll
    for (int off = 4; off <= 16; off <<= 1)
        lsum += __shfl_xor_sync(0xffffffffu, lsum, off);
    if (lane < 4) s_red[warp * 4 + lane] = lsum;
    __syncthreads();
    if (tid < 4) {
        float sm = 0.f;
#pragma unroll
        for (int w2 = 0; w2 < 8; w2++) sm += s_red[w2 * 4 + tid];
        s_inv[tid] = 1.f / sm;
    }
    __syncthreads();

    // pass 3: alpha in smem; 4 edge-slots x 64 float4 channel-groups
    int eslot = tid >> 6;
    int cg    = tid & 63;
    int hd    = cg >> 4;
    float4 acc = make_float4(0.f, 0.f, 0.f, 0.f);
    const float4* h4 = (const float4*)h;
    long baserow = (long)b * NN;

    for (int cb = 0; cb < deg; cb += 128) {
        int cnt = min(128, deg - cb);
        if (tid < cnt) s_src[tid] = g_csrsrc[start + cb + tid];
        for (int idx = tid; idx < cnt * HH; idx += 256) {
            int e = idx >> 2, h2 = idx & 3;
            int s = g_csrsrc[start + cb + e];
            float z = g_el[(b * NN + s) * HH + h2] + s_er[h2];
            z = z > 0.f ? z : 0.2f * z;
            s_alpha[idx] = expf(z - s_m[h2]) * s_inv[h2];
        }
        __syncthreads();
        for (int e = eslot; e < cnt; e += 4) {
            float a = s_alpha[e * HH + hd];
            float4 v = h4[(baserow + s_src[e]) * 64 + cg];
            acc.x += a * v.x; acc.y += a * v.y; acc.z += a * v.z; acc.w += a * v.w;
        }
        __syncthreads();
    }

    s_acc[eslot][cg] = acc;
    __syncthreads();
    if (tid < 64) {
        float4 r = s_acc[0][tid];
#pragma unroll
        for (int e = 1; e < 4; e++) {
            float4 t = s_acc[e][tid];
            r.x += t.x; r.y += t.y; r.z += t.z; r.w += t.w;
        }
        ((float4*)out)[(long)bn * 64 + tid] = r;
    }
}

// ---------------- BatchNorm (training stats over B*N), partials (no atomics) ----------------
__global__ void bnred_k(const float* __restrict__ x) {
    int t = threadIdx.x;   // channel
    float s = 0.f, q = 0.f;
    for (int r = blockIdx.x; r < ROWS; r += 256) {
        float v = x[(long)r * HDIM + t];
        s += v; q += v * v;
    }
    g_bnpart[blockIdx.x * HDIM + t]         = s;
    g_bnpart[(256 + blockIdx.x) * HDIM + t] = q;
}

__global__ void bnfin_k(const float* __restrict__ gamma, const float* __restrict__ beta) {
    int t = threadIdx.x;
    float s = 0.f, q = 0.f;
    for (int i = 0; i < 256; i++) {
        s += g_bnpart[i * HDIM + t];
        q += g_bnpart[(256 + i) * HDIM + t];
    }
    const float inv = 1.f / (float)ROWS;
    float mu  = s * inv;
    float var = q * inv - mu * mu;
    float r = rsqrtf(var + 1e-5f);
    float sc = r * gamma[t];
    g_scale[t] = sc;
    g_shift[t] = beta[t] - mu * sc;
}

__global__ void normact_k(const float* __restrict__ x, float* __restrict__ y) {
    long i = (long)blockIdx.x * blockDim.x + threadIdx.x;   // over ROWS*64 float4
    if (i >= (long)ROWS * 64) return;
    int c4 = (int)(i & 63);
    float4 v  = ((const float4*)x)[i];
    float4 sc = ((const float4*)g_scale)[c4];
    float4 sh = ((const float4*)g_shift)[c4];
    v.x = v.x * sc.x + sh.x; v.x = v.x > 0.f ? v.x : 0.01f * v.x;
    v.y = v.y * sc.y + sh.y; v.y = v.y > 0.f ? v.y : 0.01f * v.y;
    v.z = v.z * sc.z + sh.z; v.z = v.z > 0.f ? v.z : 0.01f * v.z;
    v.w = v.w * sc.w + sh.w; v.w = v.w > 0.f ? v.w : 0.01f * v.w;
    ((float4*)y)[i] = v;
}

// ---------------- output projection + xx window shift ----------------
__global__ void outproj_k(const float* __restrict__ h, const float* __restrict__ Wout,
                          const float* __restrict__ bout, float* __restrict__ dout, int step)
{
    int g = blockIdx.x*blockDim.x + threadIdx.x;
    int w = g >> 5;
    if (w >= ROWS) return;
    int lane = g & 31;
    const float* hp = h + (long)w * HDIM + lane * 8;
    float p0 = 0.f, p1 = 0.f, p2 = 0.f;
#pragma unroll
    for (int i = 0; i < 8; i++) {
        float v = hp[i];
        int c = lane * 8 + i;
        p0 += v * Wout[c * 3 + 0];
        p1 += v * Wout[c * 3 + 1];
        p2 += v * Wout[c * 3 + 2];
    }
#pragma unroll
    for (int off = 1; off < 32; off <<= 1) {
        p0 += __shfl_xor_sync(0xffffffffu, p0, off);
        p1 += __shfl_xor_sync(0xffffffffu, p1, off);
        p2 += __shfl_xor_sync(0xffffffffu, p2, off);
    }
    if (lane == 0) {
        p0 += bout[0]; p1 += bout[1]; p2 += bout[2];
        float* xr = g_xx + (long)w * INDP;
        float tmp[IND - 3];
#pragma unroll
        for (int i = 0; i < IND - 3; i++) tmp[i] = xr[i + 3];
#pragma unroll
        for (int i = 0; i < IND - 3; i++) xr[i] = tmp[i];
        xr[IND - 3] = p0; xr[IND - 2] = p1; xr[IND - 1] = p2;
        float* op = dout + ((long)w * TT + step) * OUTD;
        op[0] = p0; op[1] = p1; op[2] = p2;
    }
}

// ---------------- launcher ----------------
extern "C" void kernel_launch(void* const* d_in, const int* in_sizes, int n_in,
                              void* d_out, int out_size)
{
    const float* xx_in = (const float*)d_in[0];
    const int*   src   = (const int*)d_in[1];
    const int*   dst   = (const int*)d_in[2];
    const float *W[4], *al[4], *ar[4], *gm[4], *bt[4];
    for (int l = 0; l < 4; l++) {
        W[l]  = (const float*)d_in[3 + l*5];
        al[l] = (const float*)d_in[4 + l*5];
        ar[l] = (const float*)d_in[5 + l*5];
        gm[l] = (const float*)d_in[6 + l*5];
        bt[l] = (const float*)d_in[7 + l*5];
    }
    const float* Wout = (const float*)d_in[23];
    const float* bout = (const float*)d_in[24];
    float* dout = (float*)d_out;

    float *xxp, *w0p, *bufA, *bufB, *bufC;
    int *degp, *curp;
    cudaGetSymbolAddress((void**)&xxp,  g_xx);
    cudaGetSymbolAddress((void**)&w0p,  g_W0p);
    cudaGetSymbolAddress((void**)&bufA, g_bufA);
    cudaGetSymbolAddress((void**)&bufB, g_bufB);
    cudaGetSymbolAddress((void**)&bufC, g_bufC);
    cudaGetSymbolAddress((void**)&degp, g_deg);
    cudaGetSymbolAddress((void**)&curp, g_cursor);

    // build CSR from dst (rebuilt each call for determinism)
    zeroi_k<<<(NN + 255) / 256, 256>>>(degp, NN);
    zeroi_k<<<(NN + 255) / 256, 256>>>(curp, NN);
    hist_k<<<(EE + 255) / 256, 256>>>(dst);
    scan_k<<<1, 1024>>>();
    csr_k<<<(EE + 255) / 256, 256>>>(src, dst);

    initxx_k<<<(ROWSP*INDP + 255) / 256, 256>>>(xx_in);
    padw0_k<<<(INDP*HDIM + 255) / 256, 256>>>(W[0]);

    dim3 ggrid(HDIM / 128, ROWSP / 128);

    for (int step = 0; step < TT; step++) {
        const float* in = xxp;
        for (int l = 0; l < 4; l++) {
            const float* Bm = (l == 0) ? w0p : W[l];
            int K = (l == 0) ? INDP : HDIM;
            gemm_tf32_k<<<ggrid, 256>>>(in, Bm, bufA, K);
            elr_k<<<(ROWS * 32 + 255) / 256, 256>>>(bufA, al[l], ar[l]);
            attn_k<<<ROWS, 256>>>(bufA, bufB);
            bnred_k<<<256, 256>>>(bufB);
            bnfin_k<<<1, 256>>>(gm[l], bt[l]);
            normact_k<<<(ROWS * 64 + 255) / 256, 256>>>(bufB, bufC);
            in = bufC;
        }
        outproj_k<<<(ROWS * 32 + 255) / 256, 256>>>(bufC, Wout, bout, dout, step);
    }
}

// round 6
// speedup vs baseline: 2.0548x; 1.0010x over previous
#include <cuda_runtime.h>
#include <mma.h>
#include <math.h>

using namespace nvcuda;

// ---------------- problem constants ----------------
#define NN   5000          // nodes
#define EE   80000         // edges
#define BB   8             // batch
#define IND  30            // input feature dim
#define INDP 32            // padded K for layer-0 GEMM
#define HH   4             // heads
#define DD   64            // dim per head
#define HDIM 256           // HH*DD
#define OUTD 3
#define TT   5             // output_length
#define ROWS (BB*NN)       // 40000
#define ROWSP 40064        // padded to multiple of 128

// ---------------- device scratch ----------------
__device__ float g_xx[ROWSP*INDP];      // rolling input window, padded [ROWSP][32]
__device__ float g_W0p[INDP*HDIM];      // zero-padded W0
__device__ float g_bufA[ROWSP*HDIM];    // GEMM output h = xW
__device__ float g_bufB[ROWSP*HDIM];    // aggregation output
__device__ float g_bufC[ROWSP*HDIM];    // normalized+activated (next layer input)
__device__ float g_el[ROWS*HH];
__device__ float g_er[ROWS*HH];
__device__ int   g_deg[NN];
__device__ int   g_rowptr[NN+1];
__device__ int   g_cursor[NN];
__device__ int   g_csrsrc[EE];
__device__ float g_bnpart[2*256*HDIM];  // per-block partial sums / sq-sums
__device__ float g_scale[HDIM];
__device__ float g_shift[HDIM];

// ---------------- graph preprocessing ----------------
__global__ void zeroi_k(int* p, int n) {
    int i = blockIdx.x*blockDim.x + threadIdx.x;
    if (i < n) p[i] = 0;
}

__global__ void hist_k(const int* __restrict__ dst) {
    int e = blockIdx.x*blockDim.x + threadIdx.x;
    if (e < EE) atomicAdd(&g_deg[dst[e]], 1);
}

// single-block Hillis-Steele scan over N=5000 (5 chunks of 1024)
__global__ void scan_k() {
    __shared__ int sm[1024];
    int t = threadIdx.x;
    int run = 0;
    for (int base = 0; base < NN; base += 1024) {
        int i = base + t;
        int v = (i < NN) ? g_deg[i] : 0;
        __syncthreads();
        sm[t] = v;
        __syncthreads();
        for (int off = 1; off < 1024; off <<= 1) {
            int a = (t >= off) ? sm[t-off] : 0;
            __syncthreads();
            sm[t] += a;
            __syncthreads();
        }
        if (i < NN) g_rowptr[i+1] = run + sm[t];
        run += sm[1023];
    }
    if (t == 0) g_rowptr[0] = 0;
}

__global__ void csr_k(const int* __restrict__ src, const int* __restrict__ dst) {
    int e = blockIdx.x*blockDim.x + threadIdx.x;
    if (e < EE) {
        int d = dst[e];
        int pos = atomicAdd(&g_cursor[d], 1);
        g_csrsrc[g_rowptr[d] + pos] = src[e];
    }
}

// ---------------- init: pack xx into padded layout, pad W0 ----------------
__global__ void initxx_k(const float* __restrict__ xx) {
    int i = blockIdx.x*blockDim.x + threadIdx.x;
    if (i >= ROWSP*INDP) return;
    int r = i >> 5, c = i & 31;
    float v = 0.f;
    if (r < ROWS && c < IND) v = xx[r*IND + c];
    g_xx[i] = v;
}

__global__ void padw0_k(const float* __restrict__ W0) {
    int i = blockIdx.x*blockDim.x + threadIdx.x;
    if (i >= INDP*HDIM) return;
    int k = i / HDIM;
    g_W0p[i] = (k < IND) ? W0[i] : 0.f;
}

// ---------------- tf32-split tensor-core GEMM ----------------
// C[M=ROWSP, N=256] = A[M,K] * B[K,256], K in {32,256}, multiple of 16.
// Block tile 128x128, 8 warps (4M x 2N), warp tile 32x64.
// 2-term tf32 split (hi*hi + hi*lo + lo*hi) keeps ~fp32 accuracy.
#define LDA 20
#define LDB 136

__global__ __launch_bounds__(256, 2) void gemm_tf32_k(
    const float* __restrict__ A, const float* __restrict__ B,
    float* __restrict__ C, int K)
{
    __shared__ float As[128*LDA];
    __shared__ float Bs[16*LDB];

    int tid = threadIdx.x;
    int bx = blockIdx.x, by = blockIdx.y;
    int wid = tid >> 5;
    int wm = wid & 3;        // 0..3 -> rows wm*32
    int wn = wid >> 2;       // 0..1 -> cols wn*64

    wmma::fragment<wmma::accumulator,16,16,8,float> acc[2][4];
#pragma unroll
    for (int mi = 0; mi < 2; mi++)
#pragma unroll
        for (int ni = 0; ni < 4; ni++)
            wmma::fill_fragment(acc[mi][ni], 0.0f);

    const float* Ab = A + (long)(by * 128) * K;
    const float* Bb = B + bx * 128;

    int arow = tid >> 1, acol = (tid & 1) * 8;   // 128 rows x 16 cols
    int brow = tid >> 4, bcol = (tid & 15) * 8;  // 16 rows x 128 cols

    for (int kt = 0; kt < K; kt += 16) {
        *(float4*)&As[arow*LDA + acol]     = *(const float4*)&Ab[(long)arow*K + kt + acol];
        *(float4*)&As[arow*LDA + acol + 4] = *(const float4*)&Ab[(long)arow*K + kt + acol + 4];
        *(float4*)&Bs[brow*LDB + bcol]     = *(const float4*)&Bb[(long)(kt + brow)*HDIM + bcol];
        *(float4*)&Bs[brow*LDB + bcol + 4] = *(const float4*)&Bb[(long)(kt + brow)*HDIM + bcol + 4];
        __syncthreads();

#pragma unroll
        for (int k8 = 0; k8 < 16; k8 += 8) {
            wmma::fragment<wmma::matrix_a,16,16,8,wmma::precision::tf32,wmma::row_major> a_hi[2], a_lo[2];
#pragma unroll
            for (int mi = 0; mi < 2; mi++) {
                wmma::load_matrix_sync(a_hi[mi], &As[(wm*32 + mi*16)*LDA + k8], LDA);
#pragma unroll
                for (int t = 0; t < a_hi[mi].num_elements; t++) {
                    float x = a_hi[mi].x[t];
                    float hv = wmma::__float_to_tf32(x);
                    a_hi[mi].x[t] = hv;
                    a_lo[mi].x[t] = wmma::__float_to_tf32(x - hv);
                }
            }
#pragma unroll
            for (int ni = 0; ni < 4; ni++) {
                wmma::fragment<wmma::matrix_b,16,16,8,wmma::precision::tf32,wmma::row_major> b_hi, b_lo;
                wmma::load_matrix_sync(b_hi, &Bs[k8*LDB + wn*64 + ni*16], LDB);
#pragma unroll
                for (int t = 0; t < b_hi.num_elements; t++) {
                    float x = b_hi.x[t];
                    float hv = wmma::__float_to_tf32(x);
                    b_hi.x[t] = hv;
                    b_lo.x[t] = wmma::__float_to_tf32(x - hv);
                }
#pragma unroll
                for (int mi = 0; mi < 2; mi++) {
                    wmma::mma_sync(acc[mi][ni], a_hi[mi], b_hi, acc[mi][ni]);
                    wmma::mma_sync(acc[mi][ni], a_hi[mi], b_lo, acc[mi][ni]);
                    wmma::mma_sync(acc[mi][ni], a_lo[mi], b_hi, acc[mi][ni]);
                }
            }
        }
        __syncthreads();
    }

#pragma unroll
    for (int mi = 0; mi < 2; mi++)
#pragma unroll
        for (int ni = 0; ni < 4; ni++) {
            long row = by*128 + wm*32 + mi*16;
            int  col = bx*128 + wn*64 + ni*16;
            wmma::store_matrix_sync(&C[row*HDIM + col], acc[mi][ni], HDIM, wmma::mem_row_major);
        }
}

// ---------------- attention logits el/er: one warp per (b,n) ----------------
__global__ void elr_k(const float* __restrict__ h,
                      const float* __restrict__ al, const float* __restrict__ ar)
{
    int g = blockIdx.x*blockDim.x + threadIdx.x;
    int w = g >> 5;
    if (w >= ROWS) return;
    int lane = g & 31;
    const float4* hp  = (const float4*)(h + (long)w*HDIM) + lane*2;
    const float4* alp = (const float4*)al + lane*2;
    const float4* arp = (const float4*)ar + lane*2;
    float sl = 0.f, sr = 0.f;
#pragma unroll
    for (int i = 0; i < 2; i++) {
        float4 v = hp[i], a = alp[i], r = arp[i];
        sl += v.x*a.x + v.y*a.y + v.z*a.z + v.w*a.w;
        sr += v.x*r.x + v.y*r.y + v.z*r.z + v.w*r.w;
    }
#pragma unroll
    for (int off = 1; off < 8; off <<= 1) {
        sl += __shfl_xor_sync(0xffffffffu, sl, off);
        sr += __shfl_xor_sync(0xffffffffu, sr, off);
    }
    if ((lane & 7) == 0) {
        g_el[w * HH + (lane >> 3)] = sl;
        g_er[w * HH + (lane >> 3)] = sr;
    }
}

// ---------------- edge softmax + aggregation: one block per (b,n) ----------------
__global__ __launch_bounds__(256) void attn_k(const float* __restrict__ h,
                                              float* __restrict__ out)
{
    int bn = blockIdx.x;
    int n = bn % NN;
    int b = bn / NN;
    int tid = threadIdx.x;

    __shared__ float s_er[HH], s_m[HH], s_inv[HH];
    __shared__ float s_red[32];
    __shared__ int   s_src[128];
    __shared__ float s_alpha[128 * HH];
    __shared__ float4 s_acc[4][64];

    int start = g_rowptr[n];
    int deg   = g_rowptr[n+1] - start;

    if (tid < HH) s_er[tid] = g_er[bn * HH + tid];
    __syncthreads();

    if (deg == 0) { out[(long)bn * HDIM + tid] = 0.f; return; }

    int hh = tid & 3;
    float erh = s_er[hh];

    // pass 1: segment max
    float lmax = -1e30f;
    for (int e = tid >> 2; e < deg; e += 64) {
        int s = g_csrsrc[start + e];
        float z = g_el[(b * NN + s) * HH + hh] + erh;
        z = z > 0.f ? z : 0.2f * z;
        lmax = fmaxf(lmax, z);
    }
#pragma unroll
    for (int off = 4; off <= 16; off <<= 1)
        lmax = fmaxf(lmax, __shfl_xor_sync(0xffffffffu, lmax, off));
    int warp = tid >> 5, lane = tid & 31;
    if (lane < 4) s_red[warp * 4 + lane] = lmax;
    __syncthreads();
    if (tid < 4) {
        float m = s_red[tid];
#pragma unroll
        for (int w2 = 1; w2 < 8; w2++) m = fmaxf(m, s_red[w2 * 4 + tid]);
        s_m[tid] = m;
    }
    __syncthreads();

    // pass 2: sum of exp
    float mh = s_m[hh];
    float lsum = 0.f;
    for (int e = tid >> 2; e < deg; e += 64) {
        int s = g_csrsrc[start + e];
        float z = g_el[(b * NN + s) * HH + hh] + erh;
        z = z > 0.f ? z : 0.2f * z;
        lsum += expf(z - mh);
    }
#pragma unroll
    for (int off = 4; off <= 16; off <<= 1)
        lsum += __shfl_xor_sync(0xffffffffu, lsum, off);
    if (lane < 4) s_red[warp * 4 + lane] = lsum;
    __syncthreads();
    if (tid < 4) {
        float sm = 0.f;
#pragma unroll
        for (int w2 = 0; w2 < 8; w2++) sm += s_red[w2 * 4 + tid];
        s_inv[tid] = 1.f / sm;
    }
    __syncthreads();

    // pass 3: alpha in smem; 4 edge-slots x 64 float4 channel-groups
    int eslot = tid >> 6;
    int cg    = tid & 63;
    int hd    = cg >> 4;
    float4 acc = make_float4(0.f, 0.f, 0.f, 0.f);
    const float4* h4 = (const float4*)h;
    long baserow = (long)b * NN;

    for (int cb = 0; cb < deg; cb += 128) {
        int cnt = min(128, deg - cb);
        if (tid < cnt) s_src[tid] = g_csrsrc[start + cb + tid];
        for (int idx = tid; idx < cnt * HH; idx += 256) {
            int e = idx >> 2, h2 = idx & 3;
            int s = g_csrsrc[start + cb + e];
            float z = g_el[(b * NN + s) * HH + h2] + s_er[h2];
            z = z > 0.f ? z : 0.2f * z;
            s_alpha[idx] = expf(z - s_m[h2]) * s_inv[h2];
        }
        __syncthreads();
        for (int e = eslot; e < cnt; e += 4) {
            float a = s_alpha[e * HH + hd];
            float4 v = h4[(baserow + s_src[e]) * 64 + cg];
            acc.x += a * v.x; acc.y += a * v.y; acc.z += a * v.z; acc.w += a * v.w;
        }
        __syncthreads();
    }

    s_acc[eslot][cg] = acc;
    __syncthreads();
    if (tid < 64) {
        float4 r = s_acc[0][tid];
#pragma unroll
        for (int e = 1; e < 4; e++) {
            float4 t = s_acc[e][tid];
            r.x += t.x; r.y += t.y; r.z += t.z; r.w += t.w;
        }
        ((float4*)out)[(long)bn * 64 + tid] = r;
    }
}

// ---------------- BatchNorm (training stats over B*N), partials (no atomics) ----------------
__global__ void bnred_k(const float* __restrict__ x) {
    int t = threadIdx.x;   // channel
    float s = 0.f, q = 0.f;
    for (int r = blockIdx.x; r < ROWS; r += 256) {
        float v = x[(long)r * HDIM + t];
        s += v; q += v * v;
    }
    g_bnpart[blockIdx.x * HDIM + t]         = s;
    g_bnpart[(256 + blockIdx.x) * HDIM + t] = q;
}

__global__ void bnfin_k(const float* __restrict__ gamma, const float* __restrict__ beta) {
    int t = threadIdx.x;
    float s = 0.f, q = 0.f;
    for (int i = 0; i < 256; i++) {
        s += g_bnpart[i * HDIM + t];
        q += g_bnpart[(256 + i) * HDIM + t];
    }
    const float inv = 1.f / (float)ROWS;
    float mu  = s * inv;
    float var = q * inv - mu * mu;
    float r = rsqrtf(var + 1e-5f);
    float sc = r * gamma[t];
    g_scale[t] = sc;
    g_shift[t] = beta[t] - mu * sc;
}

__global__ void normact_k(const float* __restrict__ x, float* __restrict__ y) {
    long i = (long)blockIdx.x * blockDim.x + threadIdx.x;   // over ROWS*64 float4
    if (i >= (long)ROWS * 64) return;
    int c4 = (int)(i & 63);
    float4 v  = ((const float4*)x)[i];
    float4 sc = ((const float4*)g_scale)[c4];
    float4 sh = ((const float4*)g_shift)[c4];
    v.x = v.x * sc.x + sh.x; v.x = v.x > 0.f ? v.x : 0.01f * v.x;
    v.y = v.y * sc.y + sh.y; v.y = v.y > 0.f ? v.y : 0.01f * v.y;
    v.z = v.z * sc.z + sh.z; v.z = v.z > 0.f ? v.z : 0.01f * v.z;
    v.w = v.w * sc.w + sh.w; v.w = v.w > 0.f ? v.w : 0.01f * v.w;
    ((float4*)y)[i] = v;
}

// ---------------- output projection + xx window shift ----------------
__global__ void outproj_k(const float* __restrict__ h, const float* __restrict__ Wout,
                          const float* __restrict__ bout, float* __restrict__ dout, int step)
{
    int g = blockIdx.x*blockDim.x + threadIdx.x;
    int w = g >> 5;
    if (w >= ROWS) return;
    int lane = g & 31;
    const float* hp = h + (long)w * HDIM + lane * 8;
    float p0 = 0.f, p1 = 0.f, p2 = 0.f;
#pragma unroll
    for (int i = 0; i < 8; i++) {
        float v = hp[i];
        int c = lane * 8 + i;
        p0 += v * Wout[c * 3 + 0];
        p1 += v * Wout[c * 3 + 1];
        p2 += v * Wout[c * 3 + 2];
    }
#pragma unroll
    for (int off = 1; off < 32; off <<= 1) {
        p0 += __shfl_xor_sync(0xffffffffu, p0, off);
        p1 += __shfl_xor_sync(0xffffffffu, p1, off);
        p2 += __shfl_xor_sync(0xffffffffu, p2, off);
    }
    if (lane == 0) {
        p0 += bout[0]; p1 += bout[1]; p2 += bout[2];
        float* xr = g_xx + (long)w * INDP;
        float tmp[IND - 3];
#pragma unroll
        for (int i = 0; i < IND - 3; i++) tmp[i] = xr[i + 3];
#pragma unroll
        for (int i = 0; i < IND - 3; i++) xr[i] = tmp[i];
        xr[IND - 3] = p0; xr[IND - 2] = p1; xr[IND - 1] = p2;
        float* op = dout + ((long)w * TT + step) * OUTD;
        op[0] = p0; op[1] = p1; op[2] = p2;
    }
}

// ---------------- launcher ----------------
extern "C" void kernel_launch(void* const* d_in, const int* in_sizes, int n_in,
                              void* d_out, int out_size)
{
    const float* xx_in = (const float*)d_in[0];
    const int*   src   = (const int*)d_in[1];
    const int*   dst   = (const int*)d_in[2];
    const float *W[4], *al[4], *ar[4], *gm[4], *bt[4];
    for (int l = 0; l < 4; l++) {
        W[l]  = (const float*)d_in[3 + l*5];
        al[l] = (const float*)d_in[4 + l*5];
        ar[l] = (const float*)d_in[5 + l*5];
        gm[l] = (const float*)d_in[6 + l*5];
        bt[l] = (const float*)d_in[7 + l*5];
    }
    const float* Wout = (const float*)d_in[23];
    const float* bout = (const float*)d_in[24];
    float* dout = (float*)d_out;

    float *xxp, *w0p, *bufA, *bufB, *bufC;
    int *degp, *curp;
    cudaGetSymbolAddress((void**)&xxp,  g_xx);
    cudaGetSymbolAddress((void**)&w0p,  g_W0p);
    cudaGetSymbolAddress((void**)&bufA, g_bufA);
    cudaGetSymbolAddress((void**)&bufB, g_bufB);
    cudaGetSymbolAddress((void**)&bufC, g_bufC);
    cudaGetSymbolAddress((void**)&degp, g_deg);
    cudaGetSymbolAddress((void**)&curp, g_cursor);

    // build CSR from dst (rebuilt each call for determinism)
    zeroi_k<<<(NN + 255) / 256, 256>>>(degp, NN);
    zeroi_k<<<(NN + 255) / 256, 256>>>(curp, NN);
    hist_k<<<(EE + 255) / 256, 256>>>(dst);
    scan_k<<<1, 1024>>>();
    csr_k<<<(EE + 255) / 256, 256>>>(src, dst);

    initxx_k<<<(ROWSP*INDP + 255) / 256, 256>>>(xx_in);
    padw0_k<<<(INDP*HDIM + 255) / 256, 256>>>(W[0]);

    dim3 ggrid(HDIM / 128, ROWSP / 128);

    for (int step = 0; step < TT; step++) {
        const float* in = xxp;
        for (int l = 0; l < 4; l++) {
            const float* Bm = (l == 0) ? w0p : W[l];
            int K = (l == 0) ? INDP : HDIM;
            gemm_tf32_k<<<ggrid, 256>>>(in, Bm, bufA, K);
            elr_k<<<(ROWS * 32 + 255) / 256, 256>>>(bufA, al[l], ar[l]);
            attn_k<<<ROWS, 256>>>(bufA, bufB);
            bnred_k<<<256, 256>>>(bufB);
            bnfin_k<<<1, 256>>>(gm[l], bt[l]);
            normact_k<<<(ROWS * 64 + 255) / 256, 256>>>(bufB, bufC);
            in = bufC;
        }
        outproj_k<<<(ROWS * 32 + 255) / 256, 256>>>(bufC, Wout, bout, dout, step);
    }
}